// round 14
// baseline (speedup 1.0000x reference)
#include <cuda_runtime.h>
#include <cuda_fp8.h>
#include <cuda_bf16.h>
#include <cstdint>

// ============================================================================
// FineGrainedFP8SwiGLUMLP — Round 12: identical kernels to R11 (bf16 HMMA
// core at the legacy tensor ceiling). Launch-graph change only:
// M-split GEMM halves on priority streams so the combine kernel and the
// dual->down boundary hide inside the low-priority GEMM half's execution.
// ============================================================================

namespace {

constexpr int MM = 4096, HH = 4096, II = 14336, QB = 128;
constexpr float FP8_MAX = 448.0f;
constexpr int STAGES = 3;
constexpr int STAGE_B = 65536;                    // 32KB A + 32KB B (bf16 128x128)
constexpr int SMEM_SZ = STAGES * STAGE_B;         // 192 KB
constexpr int MH = MM / 2;                        // M half = 2048 rows

// ------------------------------- scratch -----------------------------------
__device__ int           g_flag;
__device__ __nv_bfloat16 g_xb[(size_t)MM * HH];
__device__ float         g_xs[(size_t)MM * (HH / QB)];
__device__ __nv_bfloat16 g_gw[(size_t)II * HH];
__device__ __nv_bfloat16 g_uw[(size_t)II * HH];
__device__ __nv_bfloat16 g_dw[(size_t)HH * II];
__device__ float         g_gate[(size_t)MM * II];
__device__ float         g_up[(size_t)MM * II];
__device__ __nv_bfloat16 g_hb[(size_t)MM * II];
__device__ float         g_hs[(size_t)MM * (II / QB)];

// --------------------------- PTX helpers -----------------------------------
__device__ __forceinline__ uint32_t smem_u32(const void* p) {
    uint32_t a;
    asm("{ .reg .u64 t; cvta.to.shared.u64 t, %1; cvt.u32.u64 %0, t; }" : "=r"(a) : "l"(p));
    return a;
}
__device__ __forceinline__ void cp16(uint32_t dst, const void* src) {
    asm volatile("cp.async.cg.shared.global [%0], [%1], 16;" :: "r"(dst), "l"(src));
}
__device__ __forceinline__ void ldsm4(uint32_t* r, uint32_t a) {
    asm volatile("ldmatrix.sync.aligned.m8n8.x4.shared.b16 {%0,%1,%2,%3}, [%4];"
                 : "=r"(r[0]), "=r"(r[1]), "=r"(r[2]), "=r"(r[3]) : "r"(a));
}
__device__ __forceinline__ void mma_bf16(float* d, const uint32_t* a, uint32_t b0, uint32_t b1) {
    asm volatile(
        "mma.sync.aligned.m16n8k16.row.col.f32.bf16.bf16.f32 "
        "{%0,%1,%2,%3}, {%4,%5,%6,%7}, {%8,%9}, {%0,%1,%2,%3};"
        : "+f"(d[0]), "+f"(d[1]), "+f"(d[2]), "+f"(d[3])
        : "r"(a[0]), "r"(a[1]), "r"(a[2]), "r"(a[3]), "r"(b0), "r"(b1));
}
__device__ __forceinline__ __nv_bfloat16 f8_to_bf16(uint8_t bits) {
    __nv_fp8_e4m3 v; v.__x = bits;
    return __float2bfloat16(float(v));
}

// ------------------------------ aux kernels --------------------------------
__global__ void detect_kernel(const unsigned* __restrict__ w) {
    int ok = 1;
    for (int i = threadIdx.x; i < 256; i += 32)
        if (w[i] & 0x000FFFFFu) ok = 0;
    ok = __all_sync(0xffffffffu, ok) ? 1 : 0;
    if (threadIdx.x == 0) g_flag = ok;
}

__global__ void convert_w_kernel(const void* __restrict__ w, __nv_bfloat16* __restrict__ out,
                                 size_t n4) {
    for (size_t i = (size_t)blockIdx.x * blockDim.x + threadIdx.x; i < n4;
         i += (size_t)gridDim.x * blockDim.x) {
        __nv_bfloat16 o[4];
        if (g_flag) {
            float4 v = reinterpret_cast<const float4*>(w)[i];
            o[0] = __float2bfloat16(float(__nv_fp8_e4m3(v.x)));
            o[1] = __float2bfloat16(float(__nv_fp8_e4m3(v.y)));
            o[2] = __float2bfloat16(float(__nv_fp8_e4m3(v.z)));
            o[3] = __float2bfloat16(float(__nv_fp8_e4m3(v.w)));
        } else {
            uchar4 v = reinterpret_cast<const uchar4*>(w)[i];
            o[0] = f8_to_bf16(v.x); o[1] = f8_to_bf16(v.y);
            o[2] = f8_to_bf16(v.z); o[3] = f8_to_bf16(v.w);
        }
        reinterpret_cast<uint2*>(out)[i] = *reinterpret_cast<uint2*>(o);
    }
}

// x -> bf16 quantized values + scales. One warp per (row, 128-col group).
__global__ void fq_x_kernel(const float* __restrict__ x, __nv_bfloat16* __restrict__ q,
                            float* __restrict__ sc, int cols) {
    int warp = (blockIdx.x * blockDim.x + threadIdx.x) >> 5;
    int lane = threadIdx.x & 31;
    int ng = cols / QB;
    int row = warp / ng, grp = warp % ng;
    size_t off = (size_t)row * cols + grp * QB;
    float4 v = reinterpret_cast<const float4*>(x + off)[lane];
    float amax = fmaxf(fmaxf(fabsf(v.x), fabsf(v.y)), fmaxf(fabsf(v.z), fabsf(v.w)));
#pragma unroll
    for (int o = 16; o; o >>= 1)
        amax = fmaxf(amax, __shfl_xor_sync(0xffffffffu, amax, o));
    float scale = fmaxf(amax / FP8_MAX, 1e-12f);
    __nv_bfloat16 u[4];
    u[0] = __float2bfloat16(float(__nv_fp8_e4m3(fminf(fmaxf(v.x / scale, -FP8_MAX), FP8_MAX))));
    u[1] = __float2bfloat16(float(__nv_fp8_e4m3(fminf(fmaxf(v.y / scale, -FP8_MAX), FP8_MAX))));
    u[2] = __float2bfloat16(float(__nv_fp8_e4m3(fminf(fmaxf(v.z / scale, -FP8_MAX), FP8_MAX))));
    u[3] = __float2bfloat16(float(__nv_fp8_e4m3(fminf(fmaxf(v.w / scale, -FP8_MAX), FP8_MAX))));
    reinterpret_cast<uint2*>(q + off)[lane] = *reinterpret_cast<uint2*>(u);
    if (lane == 0) sc[(size_t)row * ng + grp] = scale;
}

// hidden = fq(silu(gate)*up) -> bf16 + scales
__global__ void combine_fq_kernel(const float* __restrict__ gate, const float* __restrict__ up,
                                  __nv_bfloat16* __restrict__ q, float* __restrict__ sc, int cols) {
    int warp = (blockIdx.x * blockDim.x + threadIdx.x) >> 5;
    int lane = threadIdx.x & 31;
    int ng = cols / QB;
    int row = warp / ng, grp = warp % ng;
    size_t off = (size_t)row * cols + grp * QB;
    float4 g = reinterpret_cast<const float4*>(gate + off)[lane];
    float4 u = reinterpret_cast<const float4*>(up + off)[lane];
    float h[4];
    h[0] = g.x * (1.0f / (1.0f + expf(-g.x))) * u.x;
    h[1] = g.y * (1.0f / (1.0f + expf(-g.y))) * u.y;
    h[2] = g.z * (1.0f / (1.0f + expf(-g.z))) * u.z;
    h[3] = g.w * (1.0f / (1.0f + expf(-g.w))) * u.w;
    float amax = fmaxf(fmaxf(fabsf(h[0]), fabsf(h[1])), fmaxf(fabsf(h[2]), fabsf(h[3])));
#pragma unroll
    for (int o = 16; o; o >>= 1)
        amax = fmaxf(amax, __shfl_xor_sync(0xffffffffu, amax, o));
    float scale = fmaxf(amax / FP8_MAX, 1e-12f);
    __nv_bfloat16 o4[4];
#pragma unroll
    for (int i = 0; i < 4; i++)
        o4[i] = __float2bfloat16(float(__nv_fp8_e4m3(fminf(fmaxf(h[i] / scale, -FP8_MAX), FP8_MAX))));
    reinterpret_cast<uint2*>(q + off)[lane] = *reinterpret_cast<uint2*>(o4);
    if (lane == 0) sc[(size_t)row * ng + grp] = scale;
}

// ----------------------- shared GEMM body (untouched) ----------------------
__device__ __forceinline__ void gemm_body(
    const __nv_bfloat16* __restrict__ A, const __nv_bfloat16* __restrict__ B,
    const float* __restrict__ Asc, const float* __restrict__ Wsc,
    float* __restrict__ C, int N, int K, int nb, char* smem)
{
    const uint32_t sb = smem_u32(smem);
    const int tid = threadIdx.x, lane = tid & 31, wid = tid >> 5;
    const int wm = wid >> 2, wn = wid & 3;            // 4x4 warp grid
    const int bm = blockIdx.x * 128, bn = nb * 128;
    const int nch = K >> 7;

    auto load_stage = [&](int s, int c) {
        const uint32_t base = sb + (uint32_t)s * STAGE_B;
#pragma unroll
        for (int i = 0; i < 4; i++) {
            int idx = tid + (i << 9);                 // 0..2047
            int row = idx >> 4, ch = idx & 15;
            uint32_t dst = base + (uint32_t)(row << 8) + (uint32_t)((ch ^ (row & 7)) << 4);
            cp16(dst, A + (size_t)(bm + row) * K + c * 128 + ch * 8);
        }
#pragma unroll
        for (int i = 0; i < 4; i++) {
            int idx = tid + (i << 9);
            int row = idx >> 4, ch = idx & 15;
            uint32_t dst = base + 32768u + (uint32_t)(row << 8) + (uint32_t)((ch ^ (row & 7)) << 4);
            cp16(dst, B + (size_t)(bn + row) * K + c * 128 + ch * 8);
        }
        asm volatile("cp.async.commit_group;");
    };

    float full[2][4][4];
#pragma unroll
    for (int t = 0; t < 2; t++)
#pragma unroll
        for (int j = 0; j < 4; j++)
#pragma unroll
            for (int r = 0; r < 4; r++) full[t][j][r] = 0.0f;

    for (int c = 0; c < STAGES - 1; c++) load_stage(c, c);

    const float* wsc = Wsc + (size_t)nb * nch;

    for (int c = 0; c < nch; c++) {
        asm volatile("cp.async.wait_group %0;" :: "n"(STAGES - 2));
        __syncthreads();   // single barrier per chunk (publishes + protects reuse)

        {   // issue next chunk into the stage freed last iteration
            int cl = c + STAGES - 1;
            if (cl < nch) load_stage(cl % STAGES, cl);
            else asm volatile("cp.async.commit_group;");
        }

        const uint32_t Ab = sb + (uint32_t)(c % STAGES) * STAGE_B;
        const uint32_t Bb = Ab + 32768u;

        float cacc[2][4][4];
#pragma unroll
        for (int t = 0; t < 2; t++)
#pragma unroll
            for (int j = 0; j < 4; j++)
#pragma unroll
                for (int r = 0; r < 4; r++) cacc[t][j][r] = 0.0f;

#pragma unroll
        for (int ks = 0; ks < 8; ks++) {
            uint32_t a[2][4], b[2][4];
#pragma unroll
            for (int t = 0; t < 2; t++) {
                int mrow = wm * 32 + t * 16 + (lane & 15);
                int chn = ((ks << 1) + (lane >> 4)) ^ (mrow & 7);
                ldsm4(a[t], Ab + (uint32_t)(mrow << 8) + (uint32_t)(chn << 4));
            }
#pragma unroll
            for (int p = 0; p < 2; p++) {
                int nrow = wn * 32 + p * 16 + (lane & 15);
                int chn = ((ks << 1) + (lane >> 4)) ^ (nrow & 7);
                ldsm4(b[p], Bb + (uint32_t)(nrow << 8) + (uint32_t)(chn << 4));
            }
#pragma unroll
            for (int t = 0; t < 2; t++)
#pragma unroll
                for (int j = 0; j < 4; j++) {
                    int p = j >> 1, o = j & 1;
                    mma_bf16(cacc[t][j], a[t], b[p][o], b[p][o + 2]);
                }
        }

        // promote this 128-K block with exact fp32 scales
        const float sw = wsc[c];
#pragma unroll
        for (int t = 0; t < 2; t++)
#pragma unroll
            for (int h = 0; h < 2; h++) {
                int row = bm + wm * 32 + t * 16 + h * 8 + (lane >> 2);
                float s = Asc[(size_t)row * nch + c] * sw;
#pragma unroll
                for (int j = 0; j < 4; j++) {
                    full[t][j][2 * h]     = fmaf(s, cacc[t][j][2 * h],     full[t][j][2 * h]);
                    full[t][j][2 * h + 1] = fmaf(s, cacc[t][j][2 * h + 1], full[t][j][2 * h + 1]);
                }
            }
    }

    // plain fp32 epilogue
#pragma unroll
    for (int t = 0; t < 2; t++)
#pragma unroll
        for (int h = 0; h < 2; h++) {
            int row = bm + wm * 32 + t * 16 + h * 8 + (lane >> 2);
#pragma unroll
            for (int j = 0; j < 4; j++) {
                int col = bn + wn * 32 + j * 8 + (lane & 3) * 2;
                *reinterpret_cast<float2*>(C + (size_t)row * N + col) =
                    make_float2(full[t][j][2 * h], full[t][j][2 * h + 1]);
            }
        }
}

__global__ void __launch_bounds__(512, 1) gemm_plain_kernel(
    const __nv_bfloat16* __restrict__ A, const __nv_bfloat16* __restrict__ B,
    const float* __restrict__ Asc, const float* __restrict__ Wsc,
    float* __restrict__ C, int N, int K)
{
    extern __shared__ char smem[];
    gemm_body(A, B, Asc, Wsc, C, N, K, blockIdx.y, smem);
}

// gate & up: grid.y in [0, 2*(II/128)); y<112 -> gate, else -> up.
__global__ void __launch_bounds__(512, 1) gemm_dual_kernel(
    const __nv_bfloat16* __restrict__ A,
    const __nv_bfloat16* __restrict__ Bg, const __nv_bfloat16* __restrict__ Bu,
    const float* __restrict__ Asc,
    const float* __restrict__ Wg, const float* __restrict__ Wu,
    float* __restrict__ Cg, float* __restrict__ Cu, int K)
{
    extern __shared__ char smem[];
    const int half = II / 128;                        // 112
    const bool is_up = (int)blockIdx.y >= half;
    const __nv_bfloat16* B = is_up ? Bu : Bg;
    const float* W = is_up ? Wu : Wg;
    float* C = is_up ? Cu : Cg;
    const int nb = is_up ? (int)blockIdx.y - half : (int)blockIdx.y;
    gemm_body(A, B, Asc, W, C, II, K, nb, smem);
}

// --------------- streams / events (static init, created once) --------------
struct AsyncCtx {
    cudaStream_t s1, s2, sHi, sLo;
    cudaEvent_t e_origin, e_detect, e_gate, e_up, e_down, e_x,
                e_d0, e_d1, e_c1, e_final;
    AsyncCtx() {
        int lo, hi;
        cudaDeviceGetStreamPriorityRange(&lo, &hi);
        cudaStreamCreateWithFlags(&s1, cudaStreamNonBlocking);
        cudaStreamCreateWithFlags(&s2, cudaStreamNonBlocking);
        cudaStreamCreateWithPriority(&sHi, cudaStreamNonBlocking, hi);
        cudaStreamCreateWithPriority(&sLo, cudaStreamNonBlocking, lo);
        cudaEventCreateWithFlags(&e_origin, cudaEventDisableTiming);
        cudaEventCreateWithFlags(&e_detect, cudaEventDisableTiming);
        cudaEventCreateWithFlags(&e_gate, cudaEventDisableTiming);
        cudaEventCreateWithFlags(&e_up, cudaEventDisableTiming);
        cudaEventCreateWithFlags(&e_down, cudaEventDisableTiming);
        cudaEventCreateWithFlags(&e_x, cudaEventDisableTiming);
        cudaEventCreateWithFlags(&e_d0, cudaEventDisableTiming);
        cudaEventCreateWithFlags(&e_d1, cudaEventDisableTiming);
        cudaEventCreateWithFlags(&e_c1, cudaEventDisableTiming);
        cudaEventCreateWithFlags(&e_final, cudaEventDisableTiming);
    }
};
AsyncCtx g_ctx;

}  // namespace

// ============================================================================
extern "C" void kernel_launch(void* const* d_in, const int* in_sizes, int n_in,
                              void* d_out, int out_size) {
    const float* x  = (const float*)d_in[0];
    const void*  gw = d_in[1];
    const float* gs = (const float*)d_in[2];
    const void*  uw = d_in[3];
    const float* us = (const float*)d_in[4];
    const void*  dw = d_in[5];
    const float* ds = (const float*)d_in[6];
    float* out = (float*)d_out;

    __nv_bfloat16 *xb, *gwb, *uwb, *dwb, *hb;
    float *xs, *gate, *up, *hs;
    cudaGetSymbolAddress((void**)&xb,  g_xb);
    cudaGetSymbolAddress((void**)&xs,  g_xs);
    cudaGetSymbolAddress((void**)&gwb, g_gw);
    cudaGetSymbolAddress((void**)&uwb, g_uw);
    cudaGetSymbolAddress((void**)&dwb, g_dw);
    cudaGetSymbolAddress((void**)&gate, g_gate);
    cudaGetSymbolAddress((void**)&up,   g_up);
    cudaGetSymbolAddress((void**)&hb,  g_hb);
    cudaGetSymbolAddress((void**)&hs,  g_hs);

    cudaFuncSetAttribute(gemm_plain_kernel, cudaFuncAttributeMaxDynamicSharedMemorySize, SMEM_SZ);
    cudaFuncSetAttribute(gemm_dual_kernel,  cudaFuncAttributeMaxDynamicSharedMemorySize, SMEM_SZ);

    const size_t n4 = (size_t)II * HH / 4;
    const int ngI = II / QB;                           // 112 groups
    const int ngH = HH / QB;                           // 32 groups

    // M-half pointer offsets (row-major everywhere; same offset logic for
    // A / Asc / C keeps gemm_body's absolute-row indexing consistent)
    const size_t offXA  = (size_t)MH * HH;             // xb rows 2048.. (elements)
    const size_t offXS  = (size_t)MH * ngH;
    const size_t offGU  = (size_t)MH * II;             // gate/up/hb rows 2048..
    const size_t offHS  = (size_t)MH * ngI;
    const size_t offOUT = (size_t)MH * HH;

    // ---- fork s2 from capture origin (REQUIRED for capture) ---------------
    cudaEventRecord(g_ctx.e_origin, 0);
    cudaStreamWaitEvent(g_ctx.s2, g_ctx.e_origin, 0);

    // s2: activation quantization — depends only on x
    fq_x_kernel<<<MM * ngH / 8, 256, 0, g_ctx.s2>>>(x, xb, xs, HH);
    cudaEventRecord(g_ctx.e_x, g_ctx.s2);

    // origin: detect, then fork s1 for up/down weight conversion
    detect_kernel<<<1, 32>>>((const unsigned*)gw);
    cudaEventRecord(g_ctx.e_detect, 0);
    cudaStreamWaitEvent(g_ctx.s1, g_ctx.e_detect, 0);

    convert_w_kernel<<<2048, 256, 0, g_ctx.s1>>>(uw, uwb, n4);
    cudaEventRecord(g_ctx.e_up, g_ctx.s1);
    convert_w_kernel<<<2048, 256, 0, g_ctx.s1>>>(dw, dwb, n4);
    cudaEventRecord(g_ctx.e_down, g_ctx.s1);

    // origin: gate weights
    convert_w_kernel<<<2048, 256>>>(gw, gwb, n4);
    cudaEventRecord(g_ctx.e_gate, 0);

    // ---- dual GEMM, M-split across priority streams ------------------------
    cudaStreamWaitEvent(g_ctx.sHi, g_ctx.e_gate, 0);
    cudaStreamWaitEvent(g_ctx.sHi, g_ctx.e_up, 0);
    cudaStreamWaitEvent(g_ctx.sHi, g_ctx.e_x, 0);
    gemm_dual_kernel<<<dim3(MH / 128, 2 * ngI), 512, SMEM_SZ, g_ctx.sHi>>>(
        xb, gwb, uwb, xs, gs, us, gate, up, HH);
    cudaEventRecord(g_ctx.e_d0, g_ctx.sHi);

    cudaStreamWaitEvent(g_ctx.sLo, g_ctx.e_gate, 0);
    cudaStreamWaitEvent(g_ctx.sLo, g_ctx.e_up, 0);
    cudaStreamWaitEvent(g_ctx.sLo, g_ctx.e_x, 0);
    gemm_dual_kernel<<<dim3(MH / 128, 2 * ngI), 512, SMEM_SZ, g_ctx.sLo>>>(
        xb + offXA, gwb, uwb, xs + offXS, gs, us, gate + offGU, up + offGU, HH);
    cudaEventRecord(g_ctx.e_d1, g_ctx.sLo);

    // ---- combine halves: h0 hides under dual_h1; h1 hides under down_h0 ----
    combine_fq_kernel<<<MH * ngI / 8, 256, 0, g_ctx.sHi>>>(gate, up, hb, hs, II);

    combine_fq_kernel<<<MH * ngI / 8, 256, 0, g_ctx.sLo>>>(
        gate + offGU, up + offGU, hb + offGU, hs + offHS, II);
    cudaEventRecord(g_ctx.e_c1, g_ctx.sLo);

    // ---- down GEMM halves on sHi ------------------------------------------
    cudaStreamWaitEvent(g_ctx.sHi, g_ctx.e_down, 0);
    gemm_plain_kernel<<<dim3(MH / 128, HH / 128), 512, SMEM_SZ, g_ctx.sHi>>>(
        hb, dwb, hs, ds, out, HH, II);

    cudaStreamWaitEvent(g_ctx.sHi, g_ctx.e_c1, 0);
    gemm_plain_kernel<<<dim3(MH / 128, HH / 128), 512, SMEM_SZ, g_ctx.sHi>>>(
        hb + offGU, dwb, hs + offHS, ds, out + offOUT, HH, II);
    cudaEventRecord(g_ctx.e_final, g_ctx.sHi);

    // join everything back to the capture-origin stream
    cudaStreamWaitEvent(0, g_ctx.e_final, 0);
}

// round 16
// speedup vs baseline: 1.0364x; 1.0364x over previous
#include <cuda_runtime.h>
#include <cuda_fp8.h>
#include <cuda_bf16.h>
#include <cstdint>

// ============================================================================
// FineGrainedFP8SwiGLUMLP — Round 15: R11 configuration (whole dual GEMM —
// the R14 M-split of it regressed via L2 weight-reuse loss) + overlap ONLY at
// the combine->down boundary: combine_h1 and down_h1 on side streams so
// combine_h1 hides under down_h0 (shared down-weights => L2-safe co-run).
// ============================================================================

namespace {

constexpr int MM = 4096, HH = 4096, II = 14336, QB = 128;
constexpr float FP8_MAX = 448.0f;
constexpr int STAGES = 3;
constexpr int STAGE_B = 65536;                    // 32KB A + 32KB B (bf16 128x128)
constexpr int SMEM_SZ = STAGES * STAGE_B;         // 192 KB
constexpr int MH = MM / 2;                        // 2048-row half

// ------------------------------- scratch -----------------------------------
__device__ int           g_flag;
__device__ __nv_bfloat16 g_xb[(size_t)MM * HH];
__device__ float         g_xs[(size_t)MM * (HH / QB)];
__device__ __nv_bfloat16 g_gw[(size_t)II * HH];
__device__ __nv_bfloat16 g_uw[(size_t)II * HH];
__device__ __nv_bfloat16 g_dw[(size_t)HH * II];
__device__ float         g_gate[(size_t)MM * II];
__device__ float         g_up[(size_t)MM * II];
__device__ __nv_bfloat16 g_hb[(size_t)MM * II];
__device__ float         g_hs[(size_t)MM * (II / QB)];

// --------------------------- PTX helpers -----------------------------------
__device__ __forceinline__ uint32_t smem_u32(const void* p) {
    uint32_t a;
    asm("{ .reg .u64 t; cvta.to.shared.u64 t, %1; cvt.u32.u64 %0, t; }" : "=r"(a) : "l"(p));
    return a;
}
__device__ __forceinline__ void cp16(uint32_t dst, const void* src) {
    asm volatile("cp.async.cg.shared.global [%0], [%1], 16;" :: "r"(dst), "l"(src));
}
__device__ __forceinline__ void ldsm4(uint32_t* r, uint32_t a) {
    asm volatile("ldmatrix.sync.aligned.m8n8.x4.shared.b16 {%0,%1,%2,%3}, [%4];"
                 : "=r"(r[0]), "=r"(r[1]), "=r"(r[2]), "=r"(r[3]) : "r"(a));
}
__device__ __forceinline__ void mma_bf16(float* d, const uint32_t* a, uint32_t b0, uint32_t b1) {
    asm volatile(
        "mma.sync.aligned.m16n8k16.row.col.f32.bf16.bf16.f32 "
        "{%0,%1,%2,%3}, {%4,%5,%6,%7}, {%8,%9}, {%0,%1,%2,%3};"
        : "+f"(d[0]), "+f"(d[1]), "+f"(d[2]), "+f"(d[3])
        : "r"(a[0]), "r"(a[1]), "r"(a[2]), "r"(a[3]), "r"(b0), "r"(b1));
}
__device__ __forceinline__ __nv_bfloat16 f8_to_bf16(uint8_t bits) {
    __nv_fp8_e4m3 v; v.__x = bits;
    return __float2bfloat16(float(v));
}

// ------------------------------ aux kernels --------------------------------
__global__ void detect_kernel(const unsigned* __restrict__ w) {
    int ok = 1;
    for (int i = threadIdx.x; i < 256; i += 32)
        if (w[i] & 0x000FFFFFu) ok = 0;
    ok = __all_sync(0xffffffffu, ok) ? 1 : 0;
    if (threadIdx.x == 0) g_flag = ok;
}

__global__ void convert_w_kernel(const void* __restrict__ w, __nv_bfloat16* __restrict__ out,
                                 size_t n4) {
    for (size_t i = (size_t)blockIdx.x * blockDim.x + threadIdx.x; i < n4;
         i += (size_t)gridDim.x * blockDim.x) {
        __nv_bfloat16 o[4];
        if (g_flag) {
            float4 v = reinterpret_cast<const float4*>(w)[i];
            o[0] = __float2bfloat16(float(__nv_fp8_e4m3(v.x)));
            o[1] = __float2bfloat16(float(__nv_fp8_e4m3(v.y)));
            o[2] = __float2bfloat16(float(__nv_fp8_e4m3(v.z)));
            o[3] = __float2bfloat16(float(__nv_fp8_e4m3(v.w)));
        } else {
            uchar4 v = reinterpret_cast<const uchar4*>(w)[i];
            o[0] = f8_to_bf16(v.x); o[1] = f8_to_bf16(v.y);
            o[2] = f8_to_bf16(v.z); o[3] = f8_to_bf16(v.w);
        }
        reinterpret_cast<uint2*>(out)[i] = *reinterpret_cast<uint2*>(o);
    }
}

// x -> bf16 quantized values + scales. One warp per (row, 128-col group).
__global__ void fq_x_kernel(const float* __restrict__ x, __nv_bfloat16* __restrict__ q,
                            float* __restrict__ sc, int cols) {
    int warp = (blockIdx.x * blockDim.x + threadIdx.x) >> 5;
    int lane = threadIdx.x & 31;
    int ng = cols / QB;
    int row = warp / ng, grp = warp % ng;
    size_t off = (size_t)row * cols + grp * QB;
    float4 v = reinterpret_cast<const float4*>(x + off)[lane];
    float amax = fmaxf(fmaxf(fabsf(v.x), fabsf(v.y)), fmaxf(fabsf(v.z), fabsf(v.w)));
#pragma unroll
    for (int o = 16; o; o >>= 1)
        amax = fmaxf(amax, __shfl_xor_sync(0xffffffffu, amax, o));
    float scale = fmaxf(amax / FP8_MAX, 1e-12f);
    __nv_bfloat16 u[4];
    u[0] = __float2bfloat16(float(__nv_fp8_e4m3(fminf(fmaxf(v.x / scale, -FP8_MAX), FP8_MAX))));
    u[1] = __float2bfloat16(float(__nv_fp8_e4m3(fminf(fmaxf(v.y / scale, -FP8_MAX), FP8_MAX))));
    u[2] = __float2bfloat16(float(__nv_fp8_e4m3(fminf(fmaxf(v.z / scale, -FP8_MAX), FP8_MAX))));
    u[3] = __float2bfloat16(float(__nv_fp8_e4m3(fminf(fmaxf(v.w / scale, -FP8_MAX), FP8_MAX))));
    reinterpret_cast<uint2*>(q + off)[lane] = *reinterpret_cast<uint2*>(u);
    if (lane == 0) sc[(size_t)row * ng + grp] = scale;
}

// hidden = fq(silu(gate)*up) -> bf16 + scales
__global__ void combine_fq_kernel(const float* __restrict__ gate, const float* __restrict__ up,
                                  __nv_bfloat16* __restrict__ q, float* __restrict__ sc, int cols) {
    int warp = (blockIdx.x * blockDim.x + threadIdx.x) >> 5;
    int lane = threadIdx.x & 31;
    int ng = cols / QB;
    int row = warp / ng, grp = warp % ng;
    size_t off = (size_t)row * cols + grp * QB;
    float4 g = reinterpret_cast<const float4*>(gate + off)[lane];
    float4 u = reinterpret_cast<const float4*>(up + off)[lane];
    float h[4];
    h[0] = g.x * (1.0f / (1.0f + expf(-g.x))) * u.x;
    h[1] = g.y * (1.0f / (1.0f + expf(-g.y))) * u.y;
    h[2] = g.z * (1.0f / (1.0f + expf(-g.z))) * u.z;
    h[3] = g.w * (1.0f / (1.0f + expf(-g.w))) * u.w;
    float amax = fmaxf(fmaxf(fabsf(h[0]), fabsf(h[1])), fmaxf(fabsf(h[2]), fabsf(h[3])));
#pragma unroll
    for (int o = 16; o; o >>= 1)
        amax = fmaxf(amax, __shfl_xor_sync(0xffffffffu, amax, o));
    float scale = fmaxf(amax / FP8_MAX, 1e-12f);
    __nv_bfloat16 o4[4];
#pragma unroll
    for (int i = 0; i < 4; i++)
        o4[i] = __float2bfloat16(float(__nv_fp8_e4m3(fminf(fmaxf(h[i] / scale, -FP8_MAX), FP8_MAX))));
    reinterpret_cast<uint2*>(q + off)[lane] = *reinterpret_cast<uint2*>(o4);
    if (lane == 0) sc[(size_t)row * ng + grp] = scale;
}

// ----------------------- shared GEMM body (untouched) ----------------------
__device__ __forceinline__ void gemm_body(
    const __nv_bfloat16* __restrict__ A, const __nv_bfloat16* __restrict__ B,
    const float* __restrict__ Asc, const float* __restrict__ Wsc,
    float* __restrict__ C, int N, int K, int nb, char* smem)
{
    const uint32_t sb = smem_u32(smem);
    const int tid = threadIdx.x, lane = tid & 31, wid = tid >> 5;
    const int wm = wid >> 2, wn = wid & 3;            // 4x4 warp grid
    const int bm = blockIdx.x * 128, bn = nb * 128;
    const int nch = K >> 7;

    auto load_stage = [&](int s, int c) {
        const uint32_t base = sb + (uint32_t)s * STAGE_B;
#pragma unroll
        for (int i = 0; i < 4; i++) {
            int idx = tid + (i << 9);                 // 0..2047
            int row = idx >> 4, ch = idx & 15;
            uint32_t dst = base + (uint32_t)(row << 8) + (uint32_t)((ch ^ (row & 7)) << 4);
            cp16(dst, A + (size_t)(bm + row) * K + c * 128 + ch * 8);
        }
#pragma unroll
        for (int i = 0; i < 4; i++) {
            int idx = tid + (i << 9);
            int row = idx >> 4, ch = idx & 15;
            uint32_t dst = base + 32768u + (uint32_t)(row << 8) + (uint32_t)((ch ^ (row & 7)) << 4);
            cp16(dst, B + (size_t)(bn + row) * K + c * 128 + ch * 8);
        }
        asm volatile("cp.async.commit_group;");
    };

    float full[2][4][4];
#pragma unroll
    for (int t = 0; t < 2; t++)
#pragma unroll
        for (int j = 0; j < 4; j++)
#pragma unroll
            for (int r = 0; r < 4; r++) full[t][j][r] = 0.0f;

    for (int c = 0; c < STAGES - 1; c++) load_stage(c, c);

    const float* wsc = Wsc + (size_t)nb * nch;

    for (int c = 0; c < nch; c++) {
        asm volatile("cp.async.wait_group %0;" :: "n"(STAGES - 2));
        __syncthreads();   // single barrier per chunk (publishes + protects reuse)

        {   // issue next chunk into the stage freed last iteration
            int cl = c + STAGES - 1;
            if (cl < nch) load_stage(cl % STAGES, cl);
            else asm volatile("cp.async.commit_group;");
        }

        const uint32_t Ab = sb + (uint32_t)(c % STAGES) * STAGE_B;
        const uint32_t Bb = Ab + 32768u;

        float cacc[2][4][4];
#pragma unroll
        for (int t = 0; t < 2; t++)
#pragma unroll
            for (int j = 0; j < 4; j++)
#pragma unroll
                for (int r = 0; r < 4; r++) cacc[t][j][r] = 0.0f;

#pragma unroll
        for (int ks = 0; ks < 8; ks++) {
            uint32_t a[2][4], b[2][4];
#pragma unroll
            for (int t = 0; t < 2; t++) {
                int mrow = wm * 32 + t * 16 + (lane & 15);
                int chn = ((ks << 1) + (lane >> 4)) ^ (mrow & 7);
                ldsm4(a[t], Ab + (uint32_t)(mrow << 8) + (uint32_t)(chn << 4));
            }
#pragma unroll
            for (int p = 0; p < 2; p++) {
                int nrow = wn * 32 + p * 16 + (lane & 15);
                int chn = ((ks << 1) + (lane >> 4)) ^ (nrow & 7);
                ldsm4(b[p], Bb + (uint32_t)(nrow << 8) + (uint32_t)(chn << 4));
            }
#pragma unroll
            for (int t = 0; t < 2; t++)
#pragma unroll
                for (int j = 0; j < 4; j++) {
                    int p = j >> 1, o = j & 1;
                    mma_bf16(cacc[t][j], a[t], b[p][o], b[p][o + 2]);
                }
        }

        // promote this 128-K block with exact fp32 scales
        const float sw = wsc[c];
#pragma unroll
        for (int t = 0; t < 2; t++)
#pragma unroll
            for (int h = 0; h < 2; h++) {
                int row = bm + wm * 32 + t * 16 + h * 8 + (lane >> 2);
                float s = Asc[(size_t)row * nch + c] * sw;
#pragma unroll
                for (int j = 0; j < 4; j++) {
                    full[t][j][2 * h]     = fmaf(s, cacc[t][j][2 * h],     full[t][j][2 * h]);
                    full[t][j][2 * h + 1] = fmaf(s, cacc[t][j][2 * h + 1], full[t][j][2 * h + 1]);
                }
            }
    }

    // plain fp32 epilogue
#pragma unroll
    for (int t = 0; t < 2; t++)
#pragma unroll
        for (int h = 0; h < 2; h++) {
            int row = bm + wm * 32 + t * 16 + h * 8 + (lane >> 2);
#pragma unroll
            for (int j = 0; j < 4; j++) {
                int col = bn + wn * 32 + j * 8 + (lane & 3) * 2;
                *reinterpret_cast<float2*>(C + (size_t)row * N + col) =
                    make_float2(full[t][j][2 * h], full[t][j][2 * h + 1]);
            }
        }
}

__global__ void __launch_bounds__(512, 1) gemm_plain_kernel(
    const __nv_bfloat16* __restrict__ A, const __nv_bfloat16* __restrict__ B,
    const float* __restrict__ Asc, const float* __restrict__ Wsc,
    float* __restrict__ C, int N, int K)
{
    extern __shared__ char smem[];
    gemm_body(A, B, Asc, Wsc, C, N, K, blockIdx.y, smem);
}

// gate & up in one launch: grid.y in [0,224); y<112 -> gate, else -> up.
__global__ void __launch_bounds__(512, 1) gemm_dual_kernel(
    const __nv_bfloat16* __restrict__ A,
    const __nv_bfloat16* __restrict__ Bg, const __nv_bfloat16* __restrict__ Bu,
    const float* __restrict__ Asc,
    const float* __restrict__ Wg, const float* __restrict__ Wu,
    float* __restrict__ Cg, float* __restrict__ Cu, int K)
{
    extern __shared__ char smem[];
    const int half = II / 128;                        // 112
    const bool is_up = (int)blockIdx.y >= half;
    const __nv_bfloat16* B = is_up ? Bu : Bg;
    const float* W = is_up ? Wu : Wg;
    float* C = is_up ? Cu : Cg;
    const int nb = is_up ? (int)blockIdx.y - half : (int)blockIdx.y;
    gemm_body(A, B, Asc, W, C, II, K, nb, smem);
}

// --------------- side streams / events (static init, created once) ---------
struct AsyncCtx {
    cudaStream_t s1, s2;
    cudaEvent_t e_origin, e_detect, e_up, e_down, e_x, e_dual, e_c1, e_final;
    AsyncCtx() {
        cudaStreamCreateWithFlags(&s1, cudaStreamNonBlocking);
        cudaStreamCreateWithFlags(&s2, cudaStreamNonBlocking);
        cudaEventCreateWithFlags(&e_origin, cudaEventDisableTiming);
        cudaEventCreateWithFlags(&e_detect, cudaEventDisableTiming);
        cudaEventCreateWithFlags(&e_up, cudaEventDisableTiming);
        cudaEventCreateWithFlags(&e_down, cudaEventDisableTiming);
        cudaEventCreateWithFlags(&e_x, cudaEventDisableTiming);
        cudaEventCreateWithFlags(&e_dual, cudaEventDisableTiming);
        cudaEventCreateWithFlags(&e_c1, cudaEventDisableTiming);
        cudaEventCreateWithFlags(&e_final, cudaEventDisableTiming);
    }
};
AsyncCtx g_ctx;

}  // namespace

// ============================================================================
extern "C" void kernel_launch(void* const* d_in, const int* in_sizes, int n_in,
                              void* d_out, int out_size) {
    const float* x  = (const float*)d_in[0];
    const void*  gw = d_in[1];
    const float* gs = (const float*)d_in[2];
    const void*  uw = d_in[3];
    const float* us = (const float*)d_in[4];
    const void*  dw = d_in[5];
    const float* ds = (const float*)d_in[6];
    float* out = (float*)d_out;

    __nv_bfloat16 *xb, *gwb, *uwb, *dwb, *hb;
    float *xs, *gate, *up, *hs;
    cudaGetSymbolAddress((void**)&xb,  g_xb);
    cudaGetSymbolAddress((void**)&xs,  g_xs);
    cudaGetSymbolAddress((void**)&gwb, g_gw);
    cudaGetSymbolAddress((void**)&uwb, g_uw);
    cudaGetSymbolAddress((void**)&dwb, g_dw);
    cudaGetSymbolAddress((void**)&gate, g_gate);
    cudaGetSymbolAddress((void**)&up,   g_up);
    cudaGetSymbolAddress((void**)&hb,  g_hb);
    cudaGetSymbolAddress((void**)&hs,  g_hs);

    cudaFuncSetAttribute(gemm_plain_kernel, cudaFuncAttributeMaxDynamicSharedMemorySize, SMEM_SZ);
    cudaFuncSetAttribute(gemm_dual_kernel,  cudaFuncAttributeMaxDynamicSharedMemorySize, SMEM_SZ);

    const size_t n4 = (size_t)II * HH / 4;
    const int ngI = II / QB;                           // 112
    const int ngH = HH / QB;                           // 32

    // M-half offsets for the combine/down split
    const size_t offGU  = (size_t)MH * II;             // gate/up/hb rows 2048..
    const size_t offHS  = (size_t)MH * ngI;
    const size_t offOUT = (size_t)MH * HH;

    // ---- fork s2 from capture origin (REQUIRED for capture) ---------------
    cudaEventRecord(g_ctx.e_origin, 0);
    cudaStreamWaitEvent(g_ctx.s2, g_ctx.e_origin, 0);

    // s2: activation quantization — depends only on x
    fq_x_kernel<<<MM * ngH / 8, 256, 0, g_ctx.s2>>>(x, xb, xs, HH);
    cudaEventRecord(g_ctx.e_x, g_ctx.s2);

    // origin: detect, then fork s1 for up/down weight conversion
    detect_kernel<<<1, 32>>>((const unsigned*)gw);
    cudaEventRecord(g_ctx.e_detect, 0);
    cudaStreamWaitEvent(g_ctx.s1, g_ctx.e_detect, 0);

    convert_w_kernel<<<2048, 256, 0, g_ctx.s1>>>(uw, uwb, n4);
    cudaEventRecord(g_ctx.e_up, g_ctx.s1);
    convert_w_kernel<<<2048, 256, 0, g_ctx.s1>>>(dw, dwb, n4);
    cudaEventRecord(g_ctx.e_down, g_ctx.s1);

    // origin: gate weights
    convert_w_kernel<<<2048, 256>>>(gw, gwb, n4);

    // ---- dual GEMM (whole, origin stream — the R11 known-good config) ------
    cudaStreamWaitEvent(0, g_ctx.e_up, 0);
    cudaStreamWaitEvent(0, g_ctx.e_x, 0);
    gemm_dual_kernel<<<dim3(MM / 128, 2 * ngI), 512, SMEM_SZ>>>(
        xb, gwb, uwb, xs, gs, us, gate, up, HH);
    cudaEventRecord(g_ctx.e_dual, 0);

    // ---- combine h0 (origin), then down h0 (origin) ------------------------
    combine_fq_kernel<<<MH * ngI / 8, 256>>>(gate, up, hb, hs, II);

    cudaStreamWaitEvent(0, g_ctx.e_down, 0);
    gemm_plain_kernel<<<dim3(MH / 128, HH / 128), 512, SMEM_SZ>>>(
        hb, dwb, hs, ds, out, HH, II);

    // ---- combine h1 on s1 (hides under down_h0) ----------------------------
    cudaStreamWaitEvent(g_ctx.s1, g_ctx.e_dual, 0);
    combine_fq_kernel<<<MH * ngI / 8, 256, 0, g_ctx.s1>>>(
        gate + offGU, up + offGU, hb + offGU, hs + offHS, II);
    cudaEventRecord(g_ctx.e_c1, g_ctx.s1);

    // ---- down h1 on s2 (fills down_h0's tail; same dwb => L2-friendly) -----
    cudaStreamWaitEvent(g_ctx.s2, g_ctx.e_c1, 0);
    cudaStreamWaitEvent(g_ctx.s2, g_ctx.e_down, 0);
    gemm_plain_kernel<<<dim3(MH / 128, HH / 128), 512, SMEM_SZ, g_ctx.s2>>>(
        hb + offGU, dwb, hs + offHS, ds, out + offOUT, HH, II);
    cudaEventRecord(g_ctx.e_final, g_ctx.s2);

    // join back to the capture-origin stream
    cudaStreamWaitEvent(0, g_ctx.e_final, 0);
}